// round 2
// baseline (speedup 1.0000x reference)
#include <cuda_runtime.h>
#include <cstdint>

#define NN 50000
#define EE 800000
#define HH 128
#define RR 8

// ---------------- scratch (device globals; no allocation allowed) ----------------
__device__ float g_t[(size_t)RR * NN * HH];   // per-relation transformed features [R,N,H]
__device__ float g_xroot[(size_t)NN * HH];    // x @ root + bias
__device__ float g_hA[(size_t)NN * HH];
__device__ float g_hB[(size_t)NN * HH];
__device__ int   g_cnt[NN * RR];
__device__ float g_invc[NN * RR];
__device__ int   g_rowptr[NN + 1];
__device__ int   g_cursor[NN];
__device__ int   g_ep[EE];                    // packed src*8 + etype, CSR-sorted by dst
__device__ float g_u[2 * HH];                 // column sums of final layer (per graph)

// ---------------- f32x2 packed-FMA helpers (FFMA2; rt=1 FMA/cyc-equivalent) -------
__device__ __forceinline__ unsigned long long pk2(float lo, float hi) {
    unsigned long long r;
    asm("mov.b64 %0, {%1, %2};" : "=l"(r) : "f"(lo), "f"(hi));
    return r;
}
__device__ __forceinline__ void upk2(unsigned long long v, float& lo, float& hi) {
    asm("mov.b64 {%0, %1}, %2;" : "=f"(lo), "=f"(hi) : "l"(v));
}
__device__ __forceinline__ void fma2(unsigned long long& d, unsigned long long a, unsigned long long b) {
    asm("fma.rn.f32x2 %0, %1, %2, %0;" : "+l"(d) : "l"(a), "l"(b));
}

// ---------------- graph preprocessing ----------------
__global__ void hist_kernel(const int* __restrict__ ei, const int* __restrict__ et) {
    int e = blockIdx.x * blockDim.x + threadIdx.x;
    if (e < EE) {
        int dst = ei[EE + e];
        int r = et[e];
        atomicAdd(&g_cnt[dst * RR + r], 1);
    }
}

__global__ void invc_kernel() {
    int i = blockIdx.x * blockDim.x + threadIdx.x;
    if (i < NN * RR) {
        int c = g_cnt[i];
        g_invc[i] = 1.0f / (float)(c > 0 ? c : 1);
    }
}

// single-block scan over node degrees (sum of 8 relation counts per node)
__global__ void scan_kernel() {
    __shared__ int sh[1024];
    __shared__ int s_carry;
    int tid = threadIdx.x;
    if (tid == 0) { s_carry = 0; g_rowptr[0] = 0; }
    __syncthreads();
    for (int base = 0; base < NN; base += 1024) {
        int i = base + tid;
        int v = 0;
        if (i < NN) {
            #pragma unroll
            for (int r = 0; r < RR; r++) v += g_cnt[i * RR + r];
        }
        sh[tid] = v;
        __syncthreads();
        for (int off = 1; off < 1024; off <<= 1) {
            int t = (tid >= off) ? sh[tid - off] : 0;
            __syncthreads();
            sh[tid] += t;
            __syncthreads();
        }
        int incl = sh[tid];
        int c = s_carry;
        if (i < NN) {
            g_rowptr[i + 1] = c + incl;
            g_cursor[i]     = c + incl - v;   // exclusive start (= rowptr[i])
        }
        __syncthreads();
        if (tid == 0) s_carry = c + sh[1023];
        __syncthreads();
    }
}

__global__ void scatter_kernel(const int* __restrict__ ei, const int* __restrict__ et) {
    int e = blockIdx.x * blockDim.x + threadIdx.x;
    if (e < EE) {
        int dst = ei[EE + e];
        int pos = atomicAdd(&g_cursor[dst], 1);
        g_ep[pos] = ei[e] * RR + et[e];       // src*8 + etype
    }
}

// ---------------- batched SGEMM: z<8 -> t[z] = X@W[z]; z==8 -> xroot = X@root+bias -----
#define BM 128
#define BN 128
#define BK 8
#define TM 8
#define TN 8

__global__ __launch_bounds__(256) void gemm_kernel(
    const float* __restrict__ X, const float* __restrict__ W,
    const float* __restrict__ root, const float* __restrict__ bias)
{
    int z = blockIdx.z;
    const float* B = (z < RR) ? (W + (size_t)z * HH * HH) : root;
    float* C = (z < RR) ? (g_t + (size_t)z * NN * HH) : g_xroot;

    __shared__ float As[BK][BM];
    __shared__ float Bs[BK][BN];

    int tid = threadIdx.x;
    int rowBase = blockIdx.x * BM;
    int aRow = tid >> 1;              // 0..127
    int aCol = (tid & 1) * 4;         // 0 or 4
    int bRow = tid >> 5;              // 0..7
    int bCol = (tid & 31) * 4;        // 0..124

    int tr = (tid >> 4) * TM;         // row offset within tile
    int tc = (tid & 15) * TN;         // col offset within tile

    unsigned long long acc2[TM][TN / 2];
    #pragma unroll
    for (int i = 0; i < TM; i++)
        #pragma unroll
        for (int j = 0; j < TN / 2; j++) acc2[i][j] = 0ULL;

    for (int kb = 0; kb < HH; kb += BK) {
        int gm = rowBase + aRow;
        float4 av = make_float4(0.f, 0.f, 0.f, 0.f);
        if (gm < NN) av = *(const float4*)(X + (size_t)gm * HH + kb + aCol);
        As[aCol + 0][aRow] = av.x;
        As[aCol + 1][aRow] = av.y;
        As[aCol + 2][aRow] = av.z;
        As[aCol + 3][aRow] = av.w;

        float4 bv = *(const float4*)(B + (size_t)(kb + bRow) * HH + bCol);
        *(float4*)&Bs[bRow][bCol] = bv;
        __syncthreads();

        #pragma unroll
        for (int k = 0; k < BK; k++) {
            float4 a0 = *(const float4*)&As[k][tr];
            float4 a1 = *(const float4*)&As[k][tr + 4];
            float4 b0 = *(const float4*)&Bs[k][tc];
            float4 b1 = *(const float4*)&Bs[k][tc + 4];
            float ra[TM] = {a0.x, a0.y, a0.z, a0.w, a1.x, a1.y, a1.z, a1.w};
            unsigned long long bp[4];
            bp[0] = pk2(b0.x, b0.y);
            bp[1] = pk2(b0.z, b0.w);
            bp[2] = pk2(b1.x, b1.y);
            bp[3] = pk2(b1.z, b1.w);
            #pragma unroll
            for (int i = 0; i < TM; i++) {
                unsigned long long ad = pk2(ra[i], ra[i]);
                #pragma unroll
                for (int jp = 0; jp < 4; jp++) fma2(acc2[i][jp], ad, bp[jp]);
            }
        }
        __syncthreads();
    }

    bool addb = (z == RR);
    #pragma unroll
    for (int i = 0; i < TM; i++) {
        int gm = rowBase + tr + i;
        if (gm < NN) {
            #pragma unroll
            for (int jp = 0; jp < 2; jp++) {
                float4 o;
                upk2(acc2[i][jp * 2 + 0], o.x, o.y);
                upk2(acc2[i][jp * 2 + 1], o.z, o.w);
                if (addb) {
                    o.x += bias[tc + jp * 4 + 0];
                    o.y += bias[tc + jp * 4 + 1];
                    o.z += bias[tc + jp * 4 + 2];
                    o.w += bias[tc + jp * 4 + 3];
                }
                *(float4*)(C + (size_t)gm * HH + tc + jp * 4) = o;
            }
        }
    }
}

// ---------------- aggregation: warp per node, CSR edges, no atomics ----------------
__global__ void agg_kernel(float* __restrict__ out, int do_relu) {
    int warp = (blockIdx.x * blockDim.x + threadIdx.x) >> 5;
    int lane = threadIdx.x & 31;
    if (warp >= NN) return;

    const float4* xr = (const float4*)(g_xroot + (size_t)warp * HH);
    float4 acc = xr[lane];

    int s = g_rowptr[warp];
    int e = g_rowptr[warp + 1];
    for (int k = s; k < e; k++) {
        int p = g_ep[k];
        int src = p >> 3;
        int r = p & 7;
        float w = g_invc[warp * RR + r];
        const float4* trow = (const float4*)(g_t + ((size_t)r * NN + src) * HH);
        float4 v = trow[lane];
        acc.x += w * v.x;
        acc.y += w * v.y;
        acc.z += w * v.z;
        acc.w += w * v.w;
    }
    if (do_relu) {
        acc.x = fmaxf(acc.x, 0.f);
        acc.y = fmaxf(acc.y, 0.f);
        acc.z = fmaxf(acc.z, 0.f);
        acc.w = fmaxf(acc.w, 0.f);
    }
    ((float4*)(out + (size_t)warp * HH))[lane] = acc;
}

// ---------------- column sums of final layer output ----------------
__global__ void mean_kernel(const float* __restrict__ X, float* __restrict__ usum) {
    __shared__ float sh[256];
    int tid = threadIdx.x;
    int col = tid & 127;
    int half = tid >> 7;
    int rowsPer = (NN + gridDim.x - 1) / gridDim.x;
    int r0 = blockIdx.x * rowsPer;
    int r1 = min(NN, r0 + rowsPer);
    float local = 0.f;
    for (int r = r0 + half; r < r1; r += 2)
        local += X[(size_t)r * HH + col];
    sh[tid] = local;
    __syncthreads();
    if (tid < 128) atomicAdd(&usum[col], sh[tid] + sh[tid + 128]);
}

// ---------------- final MLP head ----------------
__global__ void fcl_kernel(const float* __restrict__ fc1w, const float* __restrict__ fc1b,
                           const float* __restrict__ fc2w, const float* __restrict__ fc2b,
                           float* __restrict__ out) {
    __shared__ float h[2 * HH];
    __shared__ float red[HH];
    int tid = threadIdx.x;
    if (tid < 2 * HH) h[tid] = g_u[tid] * (1.0f / (float)NN);
    __syncthreads();
    if (tid < HH) {
        float y = fc1b[tid];
        for (int k = 0; k < 2 * HH; k++) y += h[k] * fc1w[k * HH + tid];
        y = fmaxf(y, 0.f);
        red[tid] = y * fc2w[tid];
    }
    __syncthreads();
    for (int off = 64; off > 0; off >>= 1) {
        if (tid < off) red[tid] += red[tid + off];
        __syncthreads();
    }
    if (tid == 0) out[0] = red[0] + fc2b[0];
}

// ---------------- host orchestration ----------------
extern "C" void kernel_launch(void* const* d_in, const int* in_sizes, int n_in,
                              void* d_out, int out_size) {
    const float* x1  = (const float*)d_in[0];
    const int*   ei1 = (const int*)d_in[1];
    const int*   et1 = (const int*)d_in[2];
    const float* x2  = (const float*)d_in[3];
    const int*   ei2 = (const int*)d_in[4];
    const int*   et2 = (const int*)d_in[5];
    const float* Wl[3]    = {(const float*)d_in[6],  (const float*)d_in[9],  (const float*)d_in[12]};
    const float* rootl[3] = {(const float*)d_in[7],  (const float*)d_in[10], (const float*)d_in[13]};
    const float* biasl[3] = {(const float*)d_in[8],  (const float*)d_in[11], (const float*)d_in[14]};
    const float* fc1w = (const float*)d_in[15];
    const float* fc1b = (const float*)d_in[16];
    const float* fc2w = (const float*)d_in[17];
    const float* fc2b = (const float*)d_in[18];

    void *cnt_p, *u_p, *hA_p, *hB_p;
    cudaGetSymbolAddress(&cnt_p, g_cnt);
    cudaGetSymbolAddress(&u_p, g_u);
    cudaGetSymbolAddress(&hA_p, g_hA);
    cudaGetSymbolAddress(&hB_p, g_hB);
    float* hA = (float*)hA_p;
    float* hB = (float*)hB_p;
    float* u  = (float*)u_p;

    cudaMemsetAsync(u_p, 0, 2 * HH * sizeof(float));

    const float* xs[2]  = {x1, x2};
    const int*   eis[2] = {ei1, ei2};
    const int*   ets[2] = {et1, et2};

    dim3 gemm_grid((NN + BM - 1) / BM, 1, RR + 1);

    for (int g = 0; g < 2; g++) {
        cudaMemsetAsync(cnt_p, 0, NN * RR * sizeof(int));
        hist_kernel<<<(EE + 255) / 256, 256>>>(eis[g], ets[g]);
        invc_kernel<<<(NN * RR + 255) / 256, 256>>>();
        scan_kernel<<<1, 1024>>>();
        scatter_kernel<<<(EE + 255) / 256, 256>>>(eis[g], ets[g]);

        const float* Xin = xs[g];
        for (int l = 0; l < 3; l++) {
            gemm_kernel<<<gemm_grid, 256>>>(Xin, Wl[l], rootl[l], biasl[l]);
            float* outbuf = (l == 1) ? hB : hA;   // l0->hA, l1->hB, l2->hA
            agg_kernel<<<(NN * 32 + 255) / 256, 256>>>(outbuf, (l < 2) ? 1 : 0);
            Xin = outbuf;
        }
        mean_kernel<<<128, 256>>>(Xin, u + g * HH);
    }

    fcl_kernel<<<1, 256>>>(fc1w, fc1b, fc2w, fc2b, (float*)d_out);
}